// round 1
// baseline (speedup 1.0000x reference)
#include <cuda_runtime.h>
#include <cstdint>

#define NUM_LABELS 64

// Scratch (allocation-free rule: __device__ globals)
__device__ float g_sums[NUM_LABELS];
__device__ int   g_cnts[NUM_LABELS];
__device__ float g_delta[NUM_LABELS];

// ---------------------------------------------------------------------------
// Kernel 0: zero the accumulators (must run every launch — graph replays)
// ---------------------------------------------------------------------------
__global__ void zero_k() {
    int i = threadIdx.x;
    if (i < NUM_LABELS) { g_sums[i] = 0.0f; g_cnts[i] = 0; }
}

// ---------------------------------------------------------------------------
// Kernel 1: per-label sum+count via ONE packed 64-bit shared atomic per elem.
//   packed = (fixed_point_sum << 20) + count
//   fixed point scale 2^24; per-warp count <= ~22k << 2^20, so no carry into
//   the sum field; sum field is 44 bits signed, |sum|*2^24 < 2^43. Exact.
// ---------------------------------------------------------------------------
__global__ void __launch_bounds__(256) reduce_k(const float4* __restrict__ tex4,
                                                const int4*  __restrict__ lab4,
                                                const float* __restrict__ tex,
                                                const int*   __restrict__ lab,
                                                int n4, int n) {
    __shared__ unsigned long long acc[8][NUM_LABELS];   // per-warp private
    const int w = threadIdx.x >> 5;

    for (int i = threadIdx.x; i < 8 * NUM_LABELS; i += 256)
        (&acc[0][0])[i] = 0ull;
    __syncthreads();

    const float SCALE = 16777216.0f;  // 2^24
    int i = blockIdx.x * 256 + threadIdx.x;
    const int stride = gridDim.x * 256;
    for (; i < n4; i += stride) {
        const float4 t = tex4[i];
        const int4   l = lab4[i];
        atomicAdd(&acc[w][l.x],
                  ((unsigned long long)(long long)__float2ll_rn(t.x * SCALE) << 20) + 1ull);
        atomicAdd(&acc[w][l.y],
                  ((unsigned long long)(long long)__float2ll_rn(t.y * SCALE) << 20) + 1ull);
        atomicAdd(&acc[w][l.z],
                  ((unsigned long long)(long long)__float2ll_rn(t.z * SCALE) << 20) + 1ull);
        atomicAdd(&acc[w][l.w],
                  ((unsigned long long)(long long)__float2ll_rn(t.w * SCALE) << 20) + 1ull);
    }
    // scalar tail (n not divisible by 4), handled by block 0 only
    if (blockIdx.x == 0) {
        int t0 = n4 * 4 + threadIdx.x;
        if (t0 < n) {
            atomicAdd(&acc[w][lab[t0]],
                      ((unsigned long long)(long long)__float2ll_rn(tex[t0] * SCALE) << 20) + 1ull);
        }
    }
    __syncthreads();

    // decode + one pair of global atomics per label per block
    for (int l = threadIdx.x; l < NUM_LABELS; l += 256) {
        unsigned long long tot = 0ull;
        #pragma unroll
        for (int ww = 0; ww < 8; ww++) tot += acc[ww][l];
        unsigned int cnt = (unsigned int)(tot & 0xFFFFFull);
        long long fx = (long long)(tot - (unsigned long long)cnt) >> 20;  // arithmetic shift
        atomicAdd(&g_sums[l], (float)fx * (1.0f / 16777216.0f));
        atomicAdd(&g_cnts[l], (int)cnt);
    }
}

// ---------------------------------------------------------------------------
// Kernel 2: per-label delta = mean - intensity (label 0 untouched)
// ---------------------------------------------------------------------------
__global__ void delta_k(const float* __restrict__ inten) {
    int l = threadIdx.x;
    if (l < NUM_LABELS) {
        float m = g_sums[l] / fmaxf((float)g_cnts[l], 1.0f);
        g_delta[l] = (l > 0) ? (m - inten[l]) : 0.0f;
    }
}

// ---------------------------------------------------------------------------
// Kernel 3: out = tex - delta[lab]  (pure streaming, float4/int4)
// ---------------------------------------------------------------------------
__global__ void __launch_bounds__(256) apply_k(const float4* __restrict__ tex4,
                                               const int4*  __restrict__ lab4,
                                               float4* __restrict__ out4,
                                               const float* __restrict__ tex,
                                               const int*   __restrict__ lab,
                                               float* __restrict__ out,
                                               int n4, int n) {
    __shared__ float sd[NUM_LABELS];
    if (threadIdx.x < NUM_LABELS) sd[threadIdx.x] = g_delta[threadIdx.x];
    __syncthreads();

    int i = blockIdx.x * 256 + threadIdx.x;
    if (i < n4) {
        const float4 t = tex4[i];
        const int4   l = lab4[i];
        float4 o;
        o.x = t.x - sd[l.x];
        o.y = t.y - sd[l.y];
        o.z = t.z - sd[l.z];
        o.w = t.w - sd[l.w];
        out4[i] = o;
    }
    // scalar tail
    if (blockIdx.x == 0) {
        int t0 = n4 * 4 + threadIdx.x;
        if (t0 < n) out[t0] = tex[t0] - sd[lab[t0]];
    }
}

// ---------------------------------------------------------------------------
extern "C" void kernel_launch(void* const* d_in, const int* in_sizes, int n_in,
                              void* d_out, int out_size) {
    const float* tex   = (const float*)d_in[0];
    const int*   lab   = (const int*)  d_in[1];
    const float* inten = (const float*)d_in[2];
    float* out = (float*)d_out;

    const int n  = in_sizes[0];
    const int n4 = n >> 2;

    zero_k<<<1, 64>>>();

    // persistent-style grid for the reduction: 8 blocks/SM * 148 SMs
    const int red_blocks = 1184;
    reduce_k<<<red_blocks, 256>>>((const float4*)tex, (const int4*)lab,
                                  tex, lab, n4, n);

    delta_k<<<1, 64>>>(inten);

    int app_blocks = (n4 + 255) / 256;
    if (app_blocks < 1) app_blocks = 1;
    apply_k<<<app_blocks, 256>>>((const float4*)tex, (const int4*)lab,
                                 (float4*)out, tex, lab, out, n4, n);
}